// round 16
// baseline (speedup 1.0000x reference)
#include <cuda_runtime.h>
#include <cuda_fp16.h>
#include <math.h>

// ConvTranspose2d(64->64,k4,s2,p1)+BN+softmax(ch)+maxpool2x2.
// R15: R14 32x32 warp tiles with corrected 16B-aligned strides (72 halves =
// 144B rows; 68 caused the misaligned-address trap). Softmax partial
// exchange lives in the slab rows' padding halves (64..67), so smem =
// 74.9KB -> 3 CTAs/SM. LDSM/MMA = 0.5 (B fragments reused across 2 stripes).
//
// Parity decomposition (validated): conv out (oy=2*po+r, ox=2*qo+b), taps
// (dh,dw): ih=po+r+dh-1, iw=qo+b+dw-1, kh=3-r-2dh, kw=3-b-2dw.
// Block (pb,n): per class c=(r,b): C[m][cout], m=pl*64+q, K = 4taps x 64cin.

#define SSTR 72                       // slab row stride (halves), 144B rows
#define BSTR 72                       // B row stride (halves)
#define OFF_SLAB 0
#define OFF_B    38016                // slab = 4*66*72*2
#define SMEM_BYTES 74880              // + B = 4*64*72*2 -> 3 CTAs/SM

// Pre-transposed fp16 weights, BN scale folded: [class*4+tap][cin][cout]
__device__ __align__(16) __half wTh[16 * 4096];

__global__ void prep_weights(const float* __restrict__ w,
                             const float* __restrict__ gamma,
                             const float* __restrict__ rvar) {
    int idx = blockIdx.x * 256 + threadIdx.x;   // 65536
    int ct  = idx >> 12;
    int e   = idx & 4095;
    int cin = e >> 6, co = e & 63;
    int c = ct >> 2, tp = ct & 3;
    int r = c >> 1, b = c & 1, dh = tp >> 1, dw = tp & 1;
    float scale = gamma[co] * rsqrtf(rvar[co] + 1e-5f);
    wTh[ct * 4096 + cin * 64 + co] =
        __float2half_rn(w[(cin * 64 + co) * 16
                          + (3 - r - 2 * dh) * 4 + (3 - b - 2 * dw)] * scale);
}

__device__ __forceinline__ unsigned smem_u32(const void* p) {
    unsigned a;
    asm("{ .reg .u64 t; cvta.to.shared.u64 t, %1; cvt.u32.u64 %0, t; }"
        : "=r"(a) : "l"(p));
    return a;
}

#define LDSM4(r0, r1, r2, r3, addr) \
    asm volatile("ldmatrix.sync.aligned.m8n8.x4.shared.b16 {%0,%1,%2,%3}, [%4];" \
                 : "=r"(r0), "=r"(r1), "=r"(r2), "=r"(r3) : "r"(addr))
#define LDSM4T(r0, r1, r2, r3, addr) \
    asm volatile("ldmatrix.sync.aligned.m8n8.x4.trans.shared.b16 {%0,%1,%2,%3}, [%4];" \
                 : "=r"(r0), "=r"(r1), "=r"(r2), "=r"(r3) : "r"(addr))
#define MMA16816(d, a0, a1, a2, a3, b0, b1) \
    asm volatile("mma.sync.aligned.m16n8k16.row.col.f32.f16.f16.f32 " \
                 "{%0,%1,%2,%3},{%4,%5,%6,%7},{%8,%9},{%0,%1,%2,%3};" \
                 : "+f"((d)[0]), "+f"((d)[1]), "+f"((d)[2]), "+f"((d)[3]) \
                 : "r"(a0), "r"(a1), "r"(a2), "r"(a3), "r"(b0), "r"(b1))

extern __shared__ char smraw[];

// softmax partial (max,sum) for logical slot idx (0..255) lives in the
// padding halves [64..67] of slab row idx (8B-aligned: idx*144 + 128).
__device__ __forceinline__ float2* part_ptr(__half* slab, int idx) {
    return (float2*)(slab + idx * SSTR + 64);
}

__global__ __launch_bounds__(256, 3)
void fused_mma_kernel(const float* __restrict__ x,
                      const float* __restrict__ conv_bias,
                      const float* __restrict__ gamma,
                      const float* __restrict__ beta,
                      const float* __restrict__ rmean,
                      const float* __restrict__ rvar,
                      float* __restrict__ out)
{
    __half* slab = (__half*)(smraw + OFF_SLAB);   // [srow4][col66][SSTR]
    __half* Bsm  = (__half*)(smraw + OFF_B);      // [tap4*64][BSTR]

    const int t  = threadIdx.x;
    const int pb = blockIdx.x;
    const int n  = blockIdx.y;
    const int lane = t & 31, wid = t >> 5;
    const int g = lane >> 2, tig = lane & 3;
    const int mt = wid >> 1, nt = wid & 1;   // mt: 32-row group, nt: 32-col half
    const int pl = mt >> 1;
    const int qb = (mt & 1) * 32;

    // per-lane BN-folded bias for its 8 columns (shared by both stripes)
    float Bs8[8];
    #pragma unroll
    for (int nf = 0; nf < 4; ++nf)
        #pragma unroll
        for (int j = 0; j < 2; ++j) {
            int col = nt * 32 + nf * 8 + 2 * tig + j;
            float a = gamma[col] * rsqrtf(rvar[col] + 1e-5f);
            Bs8[nf * 2 + j] = (conv_bias[col] - rmean[col]) * a + beta[col];
        }

    // slab: rows ih = 2pb-1 .. 2pb+2; layout [srow][iw+1][cin]
    for (int i = t; i < 4 * 64 * 64; i += 256) {
        int iw   = i & 63;
        int cin  = (i >> 6) & 63;
        int srow = i >> 12;
        int ih = 2 * pb - 1 + srow;
        float v = 0.f;
        if ((unsigned)ih < 64u)
            v = x[((n * 64 + cin) * 64 + ih) * 64 + iw];
        slab[(srow * 66 + iw + 1) * SSTR + cin] = __float2half_rn(v);
    }
    for (int i = t; i < 512; i += 256) {   // halo cols 0 and 65
        int cin  = i & 63;
        int side = (i >> 6) & 1;
        int srow = i >> 7;
        slab[(srow * 66 + (side ? 65 : 0)) * SSTR + cin] = __float2half_rn(0.f);
    }

    const unsigned slabU = smem_u32(slab);
    const unsigned bsmU  = smem_u32(Bsm);
    const int arow  = ((lane >> 3) & 1) * 8 + (lane & 7);
    const int akofs = (lane >> 4) * 8;

    __half2 rmax2[2][8];

    for (int c = 0; c < 4; ++c) {
        const int r = c >> 1, b = c & 1;

        __syncthreads();   // prev class done with Bsm & part reads
        {   // stage class-c B (32KB): row = tap*64+cin, 8 float4 chunks/row
            const float4* src = (const float4*)(wTh + c * 16384);
            #pragma unroll
            for (int i = t; i < 2048; i += 256) {
                int row = i >> 3;
                int ch  = i & 7;
                *(float4*)(Bsm + row * BSTR + ch * 8) = src[i];
            }
        }
        __syncthreads();

        // accumulators init = bias: d[stripe][nf][4]
        float d[2][4][4];
        #pragma unroll
        for (int s = 0; s < 2; ++s)
            #pragma unroll
            for (int nf = 0; nf < 4; ++nf) {
                d[s][nf][0] = Bs8[2 * nf]; d[s][nf][1] = Bs8[2 * nf + 1];
                d[s][nf][2] = Bs8[2 * nf]; d[s][nf][3] = Bs8[2 * nf + 1];
            }

        #pragma unroll
        for (int tap = 0; tap < 4; ++tap) {
            const int dh = tap >> 1, dw = tap & 1;
            const unsigned aA0 = slabU +
                (((r + pl + dh) * 66 + qb + arow + b + dw) * SSTR + akofs) * 2;
            const unsigned aA1 = aA0 + 16 * SSTR * 2;   // stripe 1: +16 rows
            const unsigned bA  = bsmU +
                ((tap * 64 + arow) * BSTR + nt * 32 + akofs) * 2;
            #pragma unroll
            for (int ks = 0; ks < 4; ++ks) {
                unsigned a0, a1, a2, a3, c0, c1, c2, c3, b0, b1, b2, b3;
                LDSM4(a0, a1, a2, a3, aA0 + ks * 32);
                LDSM4(c0, c1, c2, c3, aA1 + ks * 32);
                LDSM4T(b0, b1, b2, b3, bA + ks * (16 * BSTR * 2));
                MMA16816(d[0][0], a0, a1, a2, a3, b0, b1);
                MMA16816(d[0][1], a0, a1, a2, a3, b2, b3);
                MMA16816(d[1][0], c0, c1, c2, c3, b0, b1);
                MMA16816(d[1][1], c0, c1, c2, c3, b2, b3);
                LDSM4T(b0, b1, b2, b3, bA + ks * (16 * BSTR * 2) + 32);
                MMA16816(d[0][2], a0, a1, a2, a3, b0, b1);
                MMA16816(d[0][3], a0, a1, a2, a3, b2, b3);
                MMA16816(d[1][2], c0, c1, c2, c3, b0, b1);
                MMA16816(d[1][3], c0, c1, c2, c3, b2, b3);
            }
        }

        // warp-local softmax partials per stripe (rows g / g+8 of stripe)
        float mxl[2], sml[2], mxh[2], smh[2];
        #pragma unroll
        for (int s = 0; s < 2; ++s) {
            float mxlo = d[s][0][0], mxhi = d[s][0][2];
            #pragma unroll
            for (int nf = 0; nf < 4; ++nf) {
                mxlo = fmaxf(mxlo, fmaxf(d[s][nf][0], d[s][nf][1]));
                mxhi = fmaxf(mxhi, fmaxf(d[s][nf][2], d[s][nf][3]));
            }
            mxlo = fmaxf(mxlo, __shfl_xor_sync(0xFFFFFFFFu, mxlo, 1));
            mxlo = fmaxf(mxlo, __shfl_xor_sync(0xFFFFFFFFu, mxlo, 2));
            mxhi = fmaxf(mxhi, __shfl_xor_sync(0xFFFFFFFFu, mxhi, 1));
            mxhi = fmaxf(mxhi, __shfl_xor_sync(0xFFFFFFFFu, mxhi, 2));
            float smlo = 0.f, smhi = 0.f;
            #pragma unroll
            for (int nf = 0; nf < 4; ++nf) {
                float e0 = __expf(d[s][nf][0] - mxlo); d[s][nf][0] = e0; smlo += e0;
                float e1 = __expf(d[s][nf][1] - mxlo); d[s][nf][1] = e1; smlo += e1;
                float e2 = __expf(d[s][nf][2] - mxhi); d[s][nf][2] = e2; smhi += e2;
                float e3 = __expf(d[s][nf][3] - mxhi); d[s][nf][3] = e3; smhi += e3;
            }
            smlo += __shfl_xor_sync(0xFFFFFFFFu, smlo, 1);
            smlo += __shfl_xor_sync(0xFFFFFFFFu, smlo, 2);
            smhi += __shfl_xor_sync(0xFFFFFFFFu, smhi, 1);
            smhi += __shfl_xor_sync(0xFFFFFFFFu, smhi, 2);
            if (tig == 0) {
                *part_ptr(slab, ((mt * 2 + s) * 2 + nt) * 16 + g) =
                    make_float2(mxlo, smlo);
                *part_ptr(slab, ((mt * 2 + s) * 2 + nt) * 16 + 8 + g) =
                    make_float2(mxhi, smhi);
            }
            mxl[s] = mxlo; sml[s] = smlo; mxh[s] = mxhi; smh[s] = smhi;
        }
        __syncthreads();

        #pragma unroll
        for (int s = 0; s < 2; ++s) {
            const float2 plo = *part_ptr(slab, ((mt * 2 + s) * 2 + (nt ^ 1)) * 16 + g);
            const float2 phi = *part_ptr(slab, ((mt * 2 + s) * 2 + (nt ^ 1)) * 16 + 8 + g);
            const float Mlo = fmaxf(mxl[s], plo.x);
            const float Mhi = fmaxf(mxh[s], phi.x);
            const float elo = __expf(mxl[s] - Mlo);
            const float ehi = __expf(mxh[s] - Mhi);
            const float sclo = elo / (sml[s] * elo + plo.y * __expf(plo.x - Mlo));
            const float schi = ehi / (smh[s] * ehi + phi.y * __expf(phi.x - Mhi));

            if (c == 0) {
                #pragma unroll
                for (int nf = 0; nf < 4; ++nf) {
                    rmax2[s][nf]     = __floats2half2_rn(d[s][nf][0] * sclo,
                                                         d[s][nf][1] * sclo);
                    rmax2[s][4 + nf] = __floats2half2_rn(d[s][nf][2] * schi,
                                                         d[s][nf][3] * schi);
                }
            } else if (c < 3) {
                #pragma unroll
                for (int nf = 0; nf < 4; ++nf) {
                    rmax2[s][nf]     = __hmax2(rmax2[s][nf],
                        __floats2half2_rn(d[s][nf][0] * sclo, d[s][nf][1] * sclo));
                    rmax2[s][4 + nf] = __hmax2(rmax2[s][4 + nf],
                        __floats2half2_rn(d[s][nf][2] * schi, d[s][nf][3] * schi));
                }
            } else {
                const int mlo = mt * 32 + s * 16 + g;
                const int mhi = mlo + 8;
                const int polo = 2 * pb + (mlo >> 6), qlo = mlo & 63;
                const int pohi = 2 * pb + (mhi >> 6), qhi = mhi & 63;
                #pragma unroll
                for (int nf = 0; nf < 4; ++nf) {
                    const int col0 = nt * 32 + nf * 8 + 2 * tig;
                    float r0 = fmaxf(__low2float(rmax2[s][nf]),      d[s][nf][0] * sclo);
                    float r1 = fmaxf(__high2float(rmax2[s][nf]),     d[s][nf][1] * sclo);
                    float r2 = fmaxf(__low2float(rmax2[s][4 + nf]),  d[s][nf][2] * schi);
                    float r3 = fmaxf(__high2float(rmax2[s][4 + nf]), d[s][nf][3] * schi);
                    out[((n * 64 + col0)     * 64 + polo) * 64 + qlo] = r0;
                    out[((n * 64 + col0 + 1) * 64 + polo) * 64 + qlo] = r1;
                    out[((n * 64 + col0)     * 64 + pohi) * 64 + qhi] = r2;
                    out[((n * 64 + col0 + 1) * 64 + pohi) * 64 + qhi] = r3;
                }
            }
        }
    }
}

extern "C" void kernel_launch(void* const* d_in, const int* in_sizes, int n_in,
                              void* d_out, int out_size)
{
    const float* x         = (const float*)d_in[0];
    const float* w         = (const float*)d_in[1];
    const float* conv_bias = (const float*)d_in[2];
    const float* gamma     = (const float*)d_in[3];
    const float* beta      = (const float*)d_in[4];
    const float* rmean     = (const float*)d_in[5];
    const float* rvar      = (const float*)d_in[6];
    float* out             = (float*)d_out;

    prep_weights<<<256, 256>>>(w, gamma, rvar);

    cudaFuncSetAttribute(fused_mma_kernel,
                         cudaFuncAttributeMaxDynamicSharedMemorySize, SMEM_BYTES);
    dim3 grid(32, 32);
    fused_mma_kernel<<<grid, 256, SMEM_BYTES>>>(
        x, conv_bias, gamma, beta, rmean, rvar, out);
}

// round 17
// speedup vs baseline: 1.2455x; 1.2455x over previous
#include <cuda_runtime.h>
#include <cuda_fp16.h>
#include <math.h>

// ConvTranspose2d(64->64,k4,s2,p1)+BN+softmax(ch)+maxpool2x2.
// R16 = R13 (best: 96.8us; 512 thr, 16 warps, 16x32 tiles, regs<=64,
// 2 CTAs/SM) + double-buffered B staging: class c+1's LDG->STS issued
// before class c's mainloop (hidden under MMA), 2 syncs/class instead of 3.
//
// Parity decomposition (validated): conv out (oy=2*po+r, ox=2*qo+b), taps
// (dh,dw): ih=po+r+dh-1, iw=qo+b+dw-1, kh=3-r-2dh, kw=3-b-2dw.
// Block (pb,n): per class c=(r,b): C[m][cout], m=pl*64+q, K = 4taps x 64cin.

#define SSTR 72                       // slab row stride (halves), 144B rows
#define BSTR 72                       // B row stride (halves)
#define OFF_SLAB 0
#define OFF_B0   38016                // slab = 4*66*72*2
#define OFF_B1   74880                // +36864
#define OFF_PART 111744               // +36864
#define SMEM_BYTES 113792             // +2048  -> 2 CTAs/SM

// Pre-transposed fp16 weights, BN scale folded: [class*4+tap][cin][cout]
__device__ __align__(16) __half wTh[16 * 4096];

__global__ void prep_weights(const float* __restrict__ w,
                             const float* __restrict__ gamma,
                             const float* __restrict__ rvar) {
    int idx = blockIdx.x * 256 + threadIdx.x;   // 65536
    int ct  = idx >> 12;
    int e   = idx & 4095;
    int cin = e >> 6, co = e & 63;
    int c = ct >> 2, tp = ct & 3;
    int r = c >> 1, b = c & 1, dh = tp >> 1, dw = tp & 1;
    float scale = gamma[co] * rsqrtf(rvar[co] + 1e-5f);
    wTh[ct * 4096 + cin * 64 + co] =
        __float2half_rn(w[(cin * 64 + co) * 16
                          + (3 - r - 2 * dh) * 4 + (3 - b - 2 * dw)] * scale);
}

__device__ __forceinline__ unsigned smem_u32(const void* p) {
    unsigned a;
    asm("{ .reg .u64 t; cvta.to.shared.u64 t, %1; cvt.u32.u64 %0, t; }"
        : "=r"(a) : "l"(p));
    return a;
}

#define LDSM4(r0, r1, r2, r3, addr) \
    asm volatile("ldmatrix.sync.aligned.m8n8.x4.shared.b16 {%0,%1,%2,%3}, [%4];" \
                 : "=r"(r0), "=r"(r1), "=r"(r2), "=r"(r3) : "r"(addr))
#define LDSM4T(r0, r1, r2, r3, addr) \
    asm volatile("ldmatrix.sync.aligned.m8n8.x4.trans.shared.b16 {%0,%1,%2,%3}, [%4];" \
                 : "=r"(r0), "=r"(r1), "=r"(r2), "=r"(r3) : "r"(addr))
#define MMA16816(d, a0, a1, a2, a3, b0, b1) \
    asm volatile("mma.sync.aligned.m16n8k16.row.col.f32.f16.f16.f32 " \
                 "{%0,%1,%2,%3},{%4,%5,%6,%7},{%8,%9},{%0,%1,%2,%3};" \
                 : "+f"((d)[0]), "+f"((d)[1]), "+f"((d)[2]), "+f"((d)[3]) \
                 : "r"(a0), "r"(a1), "r"(a2), "r"(a3), "r"(b0), "r"(b1))

extern __shared__ char smraw[];

__global__ __launch_bounds__(512, 2)
void fused_mma_kernel(const float* __restrict__ x,
                      const float* __restrict__ conv_bias,
                      const float* __restrict__ gamma,
                      const float* __restrict__ beta,
                      const float* __restrict__ rmean,
                      const float* __restrict__ rvar,
                      float* __restrict__ out)
{
    __half*  slab = (__half*)(smraw + OFF_SLAB);   // [srow4][col66][SSTR]
    float2*  part = (float2*)(smraw + OFF_PART);   // [mt8][nt2][row16]
    __half*  Bbuf[2] = { (__half*)(smraw + OFF_B0), (__half*)(smraw + OFF_B1) };

    const int t  = threadIdx.x;
    const int pb = blockIdx.x;
    const int n  = blockIdx.y;
    const int lane = t & 31, wid = t >> 5;
    const int g = lane >> 2, tig = lane & 3;
    const int mt = wid >> 1, nt = wid & 1;
    const int m0 = mt * 16;
    const int pl = mt >> 2;
    const int q0 = (mt & 3) * 16;

    // per-lane BN-folded bias for its 8 columns
    float Bs8[8];
    #pragma unroll
    for (int nf = 0; nf < 4; ++nf)
        #pragma unroll
        for (int j = 0; j < 2; ++j) {
            int col = nt * 32 + nf * 8 + 2 * tig + j;
            float a = gamma[col] * rsqrtf(rvar[col] + 1e-5f);
            Bs8[nf * 2 + j] = (conv_bias[col] - rmean[col]) * a + beta[col];
        }

    // slab: rows ih = 2pb-1 .. 2pb+2; layout [srow][iw+1][cin]
    for (int i = t; i < 4 * 64 * 64; i += 512) {
        int iw   = i & 63;
        int cin  = (i >> 6) & 63;
        int srow = i >> 12;
        int ih = 2 * pb - 1 + srow;
        float v = 0.f;
        if ((unsigned)ih < 64u)
            v = x[((n * 64 + cin) * 64 + ih) * 64 + iw];
        slab[(srow * 66 + iw + 1) * SSTR + cin] = __float2half_rn(v);
    }
    {   // halo cols 0 and 65 (512 entries, one per thread)
        int cin  = t & 63;
        int side = (t >> 6) & 1;
        int srow = t >> 7;
        slab[(srow * 66 + (side ? 65 : 0)) * SSTR + cin] = __float2half_rn(0.f);
    }

    // prologue: stage class 0 B into buffer 0 (2048 float4, 4/thread)
    {
        const float4* src = (const float4*)(wTh);
        #pragma unroll
        for (int i = t; i < 2048; i += 512) {
            int row = i >> 3, ch = i & 7;
            *(float4*)(Bbuf[0] + row * BSTR + ch * 8) = src[i];
        }
    }
    __syncthreads();

    const unsigned slabU = smem_u32(slab);
    const unsigned bsmU[2] = { smem_u32(Bbuf[0]), smem_u32(Bbuf[1]) };
    const int arow  = ((lane >> 3) & 1) * 8 + (lane & 7);
    const int akofs = (lane >> 4) * 8;

    __half2 rmax2[8];

    for (int c = 0; c < 4; ++c) {
        const int r = c >> 1, b = c & 1;
        const int buf = c & 1;

        // issue next class's staging into the other buffer (hidden under MMA)
        if (c < 3) {
            const float4* src = (const float4*)(wTh + (c + 1) * 16384);
            __half* dst = Bbuf[buf ^ 1];
            #pragma unroll
            for (int i = t; i < 2048; i += 512) {
                int row = i >> 3, ch = i & 7;
                *(float4*)(dst + row * BSTR + ch * 8) = src[i];
            }
        }

        // accumulators init = bias (4 n8-frags x 4 regs)
        float d[4][4];
        #pragma unroll
        for (int nf = 0; nf < 4; ++nf) {
            d[nf][0] = Bs8[2 * nf];     d[nf][1] = Bs8[2 * nf + 1];
            d[nf][2] = Bs8[2 * nf];     d[nf][3] = Bs8[2 * nf + 1];
        }

        #pragma unroll
        for (int tap = 0; tap < 4; ++tap) {
            const int dh = tap >> 1, dw = tap & 1;
            const unsigned aAddr = slabU +
                (((r + pl + dh) * 66 + q0 + arow + b + dw) * SSTR + akofs) * 2;
            const unsigned bAddr = bsmU[buf] +
                ((tap * 64 + arow) * BSTR + nt * 32 + akofs) * 2;
            #pragma unroll
            for (int ks = 0; ks < 4; ++ks) {
                unsigned a0, a1, a2, a3, b0, b1, b2, b3;
                LDSM4(a0, a1, a2, a3, aAddr + ks * 32);
                LDSM4T(b0, b1, b2, b3, bAddr + ks * (16 * BSTR * 2));
                MMA16816(d[0], a0, a1, a2, a3, b0, b1);
                MMA16816(d[1], a0, a1, a2, a3, b2, b3);
                LDSM4T(b0, b1, b2, b3, bAddr + ks * (16 * BSTR * 2) + 32);
                MMA16816(d[2], a0, a1, a2, a3, b0, b1);
                MMA16816(d[3], a0, a1, a2, a3, b2, b3);
            }
        }

        // softmax partials over this warp's 32 cols (rows g and g+8)
        float mxlo = d[0][0], mxhi = d[0][2];
        #pragma unroll
        for (int nf = 0; nf < 4; ++nf) {
            mxlo = fmaxf(mxlo, fmaxf(d[nf][0], d[nf][1]));
            mxhi = fmaxf(mxhi, fmaxf(d[nf][2], d[nf][3]));
        }
        mxlo = fmaxf(mxlo, __shfl_xor_sync(0xFFFFFFFFu, mxlo, 1));
        mxlo = fmaxf(mxlo, __shfl_xor_sync(0xFFFFFFFFu, mxlo, 2));
        mxhi = fmaxf(mxhi, __shfl_xor_sync(0xFFFFFFFFu, mxhi, 1));
        mxhi = fmaxf(mxhi, __shfl_xor_sync(0xFFFFFFFFu, mxhi, 2));
        float smlo = 0.f, smhi = 0.f;
        #pragma unroll
        for (int nf = 0; nf < 4; ++nf) {
            float e0 = __expf(d[nf][0] - mxlo); d[nf][0] = e0; smlo += e0;
            float e1 = __expf(d[nf][1] - mxlo); d[nf][1] = e1; smlo += e1;
            float e2 = __expf(d[nf][2] - mxhi); d[nf][2] = e2; smhi += e2;
            float e3 = __expf(d[nf][3] - mxhi); d[nf][3] = e3; smhi += e3;
        }
        smlo += __shfl_xor_sync(0xFFFFFFFFu, smlo, 1);
        smlo += __shfl_xor_sync(0xFFFFFFFFu, smlo, 2);
        smhi += __shfl_xor_sync(0xFFFFFFFFu, smhi, 1);
        smhi += __shfl_xor_sync(0xFFFFFFFFu, smhi, 2);

        if (tig == 0) {
            part[(mt * 2 + nt) * 16 + g]     = make_float2(mxlo, smlo);
            part[(mt * 2 + nt) * 16 + 8 + g] = make_float2(mxhi, smhi);
        }
        __syncthreads();   // part(c) + staged B(c+1) visible
        const float2 plo = part[(mt * 2 + (nt ^ 1)) * 16 + g];
        const float2 phi = part[(mt * 2 + (nt ^ 1)) * 16 + 8 + g];
        const float Mlo = fmaxf(mxlo, plo.x);
        const float Mhi = fmaxf(mxhi, phi.x);
        const float elo = __expf(mxlo - Mlo);
        const float ehi = __expf(mxhi - Mhi);
        const float sclo = elo / (smlo * elo + plo.y * __expf(plo.x - Mlo));
        const float schi = ehi / (smhi * ehi + phi.y * __expf(phi.x - Mhi));

        if (c == 0) {
            #pragma unroll
            for (int nf = 0; nf < 4; ++nf) {
                rmax2[nf]     = __floats2half2_rn(d[nf][0] * sclo, d[nf][1] * sclo);
                rmax2[4 + nf] = __floats2half2_rn(d[nf][2] * schi, d[nf][3] * schi);
            }
        } else if (c < 3) {
            #pragma unroll
            for (int nf = 0; nf < 4; ++nf) {
                rmax2[nf]     = __hmax2(rmax2[nf],
                    __floats2half2_rn(d[nf][0] * sclo, d[nf][1] * sclo));
                rmax2[4 + nf] = __hmax2(rmax2[4 + nf],
                    __floats2half2_rn(d[nf][2] * schi, d[nf][3] * schi));
            }
        } else {
            const int mlo = m0 + g,  mhi = m0 + 8 + g;
            const int polo = 2 * pb + (mlo >> 6), qlo = mlo & 63;
            const int pohi = 2 * pb + (mhi >> 6), qhi = mhi & 63;
            #pragma unroll
            for (int nf = 0; nf < 4; ++nf) {
                const int col0 = nt * 32 + nf * 8 + 2 * tig;
                float r0 = fmaxf(__low2float(rmax2[nf]),      d[nf][0] * sclo);
                float r1 = fmaxf(__high2float(rmax2[nf]),     d[nf][1] * sclo);
                float r2 = fmaxf(__low2float(rmax2[4 + nf]),  d[nf][2] * schi);
                float r3 = fmaxf(__high2float(rmax2[4 + nf]), d[nf][3] * schi);
                out[((n * 64 + col0)     * 64 + polo) * 64 + qlo] = r0;
                out[((n * 64 + col0 + 1) * 64 + polo) * 64 + qlo] = r1;
                out[((n * 64 + col0)     * 64 + pohi) * 64 + qhi] = r2;
                out[((n * 64 + col0 + 1) * 64 + pohi) * 64 + qhi] = r3;
            }
        }
        if (c < 3) __syncthreads();   // part reads done before next writes
    }
}

extern "C" void kernel_launch(void* const* d_in, const int* in_sizes, int n_in,
                              void* d_out, int out_size)
{
    const float* x         = (const float*)d_in[0];
    const float* w         = (const float*)d_in[1];
    const float* conv_bias = (const float*)d_in[2];
    const float* gamma     = (const float*)d_in[3];
    const float* beta      = (const float*)d_in[4];
    const float* rmean     = (const float*)d_in[5];
    const float* rvar      = (const float*)d_in[6];
    float* out             = (float*)d_out;

    prep_weights<<<256, 256>>>(w, gamma, rvar);

    cudaFuncSetAttribute(fused_mma_kernel,
                         cudaFuncAttributeMaxDynamicSharedMemorySize, SMEM_BYTES);
    dim3 grid(32, 32);
    fused_mma_kernel<<<grid, 512, SMEM_BYTES>>>(
        x, conv_bias, gamma, beta, rmean, rvar, out);
}